// round 3
// baseline (speedup 1.0000x reference)
#include <cuda_runtime.h>
#include <cstdint>
#include <cstddef>

// Problem constants
#define B_DIM   32
#define IN_DIM  4096
#define OUT_DIM 14336

// Tiling
#define KSPLIT   16
#define O_BLK    256
#define K_BLK    32
#define NTHREADS 128
#define K_PER_SPLIT (IN_DIM / KSPLIT)   // 256
#define CHUNKS      (K_PER_SPLIT / K_BLK) // 8

// Split-K partial buffer: [KSPLIT][B][OUT] fp32 = 29.4 MB (static, no alloc)
__device__ float g_part[(size_t)KSPLIT * B_DIM * OUT_DIM];

__constant__ float c_nf4[16] = {
    -1.0f, -0.6961928009986877f, -0.5250730514526367f, -0.39491748809814453f,
    -0.28444138169288635f, -0.18477343022823334f, -0.09105003625154495f, 0.0f,
    0.07958029955625534f, 0.16093020141124725f, 0.24611230194568634f,
    0.33791524171829224f, 0.44070982933044434f, 0.5626170039176941f,
    0.7229568362236023f, 1.0f};

// Packed 2xFP32 FMA (sm_100+ only; ptxas never auto-fuses this from C++)
#define FMA2(d, a, b) asm("fma.rn.f32x2 %0, %1, %2, %0;" : "+l"(d) : "l"(a), "l"(b))
#define BCAST2(d, f)  asm("mov.b64 %0, {%1, %1};" : "=l"(d) : "r"(__float_as_uint(f)))

// ----------------------------------------------------------------------------
// GEMM-partial kernel.
//   grid = (OUT_DIM/O_BLK = 56, KSPLIT = 16), block = 128 threads
//   Each block: outputs [o0, o0+256) x all 32 batch rows, K range of 256.
//   Thread (og = tid&31, bg = tid>>5) owns an 8o x 8b register tile:
//     o in {o0 + og*4 + t} U {o0 + 128 + og*4 + t},  t<4
//     b in {bg*4 + t}     U {16 + bg*4 + t}
// ----------------------------------------------------------------------------
__global__ __launch_bounds__(NTHREADS, 3)
void nf4_gemm_partial(const float* __restrict__ x,
                      const int*   __restrict__ codes,
                      const float* __restrict__ absmax)
{
    // Dequantized W tile, layout ws[k][swizzled c4][4]:
    //   value w(k, o) stored at ws[k*256 + (((o>>2) + (k>>2)) & 63)*4 + (o&3)]
    // The (k>>2) rotation makes both the staging STS (k varies, o fixed) and
    // the inner LDS.128 (o varies, k fixed) conflict-free.
    __shared__ __align__(16) float ws[K_BLK * 256];     // 32 KB
    __shared__ __align__(16) float xs[K_BLK][36];       // transposed x, padded

    const int tid = threadIdx.x;
    const int og  = tid & 31;          // warp lane; also o-group (32 groups)
    const int bg  = tid >> 5;          // warp id = b-group (4 groups)
    const int o0  = blockIdx.x * O_BLK;
    const int kz  = blockIdx.y;
    const int k_base = kz * K_PER_SPLIT;

    // NF4 codebook held in a register per lane; lookup via warp shuffle.
    const float nf4 = c_nf4[og & 15];

    const int b_lo = bg << 2;
    const int b_hi = 16 + (bg << 2);

    // Accumulators: packed f32x2.
    //   acc[0][j] = (o+0, o+1) low half,  acc[1][j] = (o+2, o+3) low half
    //   acc[2..3][j] = same for the +128 half.  j = 0..7 -> 8 b values.
    unsigned long long acc[4][8];
#pragma unroll
    for (int p = 0; p < 4; ++p)
#pragma unroll
        for (int j = 0; j < 8; ++j) acc[p][j] = 0ull;

    for (int c = 0; c < CHUNKS; ++c) {
        const int kc = k_base + c * K_BLK;   // chunk base (multiple of 32)
        __syncthreads();                      // previous inner reads done

        // -------- stage W: dequant 32k x 256o codes into smem --------
        // 2048 int4 loads; idx -> (o_i = idx>>3, k4 = idx&7); coalesced LDG.
#pragma unroll 4
        for (int p = 0; p < 16; ++p) {
            const int idx = p * NTHREADS + tid;
            const int o_i = idx >> 3;
            const int k4  = idx & 7;
            const int4 cc = *reinterpret_cast<const int4*>(
                codes + (size_t)(o0 + o_i) * IN_DIM + kc + (k4 << 2));
            // absmax block index: (o*4096 + k)/64; kc%64 in {0,32}, k<32 -> kc>>6 const
            const float amax = absmax[(o0 + o_i) * (IN_DIM / 64) + (kc >> 6)];
            const int col4 = ((((o_i >> 2) + k4) & 63) << 2) + (o_i & 3);
            float* wp = ws + col4;
            const int kr = k4 << 2;
            wp[(kr + 0) * 256] = __shfl_sync(0xffffffffu, nf4, cc.x & 15) * amax;
            wp[(kr + 1) * 256] = __shfl_sync(0xffffffffu, nf4, cc.y & 15) * amax;
            wp[(kr + 2) * 256] = __shfl_sync(0xffffffffu, nf4, cc.z & 15) * amax;
            wp[(kr + 3) * 256] = __shfl_sync(0xffffffffu, nf4, cc.w & 15) * amax;
        }

        // -------- stage x: transpose [32][32] chunk into xs[k][b] --------
#pragma unroll
        for (int p = 0; p < 2; ++p) {
            const int idx = p * NTHREADS + tid;   // 0..255
            const int b  = idx >> 3;
            const int k4 = idx & 7;
            const float4 xv = *reinterpret_cast<const float4*>(
                x + (size_t)b * IN_DIM + kc + (k4 << 2));
            xs[(k4 << 2) + 0][b] = xv.x;
            xs[(k4 << 2) + 1][b] = xv.y;
            xs[(k4 << 2) + 2][b] = xv.z;
            xs[(k4 << 2) + 3][b] = xv.w;
        }
        __syncthreads();

        // -------- inner: 32 k-steps, 64 FMA / thread / k --------
#pragma unroll 4
        for (int k = 0; k < K_BLK; ++k) {
            const int kq = k >> 2;
            const float* wrow = ws + k * 256;
            const ulonglong2 wl = *reinterpret_cast<const ulonglong2*>(
                wrow + (((og + kq) & 63) << 2));
            const ulonglong2 wh = *reinterpret_cast<const ulonglong2*>(
                wrow + (((og + 32 + kq) & 63) << 2));
            const float4 xl = *reinterpret_cast<const float4*>(&xs[k][b_lo]);
            const float4 xh = *reinterpret_cast<const float4*>(&xs[k][b_hi]);
            const float xv[8] = {xl.x, xl.y, xl.z, xl.w, xh.x, xh.y, xh.z, xh.w};
#pragma unroll
            for (int j = 0; j < 8; ++j) {
                unsigned long long xp;
                BCAST2(xp, xv[j]);
                FMA2(acc[0][j], wl.x, xp);
                FMA2(acc[1][j], wl.y, xp);
                FMA2(acc[2][j], wh.x, xp);
                FMA2(acc[3][j], wh.y, xp);
            }
        }
    }

    // -------- epilogue: write partials [kz][b][o], 16B stores --------
    const size_t obase = (size_t)o0 + ((size_t)og << 2);
#pragma unroll
    for (int j = 0; j < 8; ++j) {
        const int b = (j < 4) ? (b_lo + j) : (b_hi + (j - 4));
        float* p = g_part + (size_t)(kz * B_DIM + b) * OUT_DIM + obase;
        ulonglong2 v0; v0.x = acc[0][j]; v0.y = acc[1][j];
        ulonglong2 v1; v1.x = acc[2][j]; v1.y = acc[3][j];
        *reinterpret_cast<ulonglong2*>(p)       = v0;   // o .. o+3
        *reinterpret_cast<ulonglong2*>(p + 128) = v1;   // o+128 .. o+131
    }
}

// ----------------------------------------------------------------------------
// Split-K reduction + bias. Deterministic (no atomics). Writes every output.
// ----------------------------------------------------------------------------
__global__ __launch_bounds__(256)
void nf4_reduce(const float* __restrict__ bias, float* __restrict__ out)
{
    const int idx = blockIdx.x * blockDim.x + threadIdx.x;  // float4 index
    const int o4  = idx % (OUT_DIM / 4);
    const int b   = idx / (OUT_DIM / 4);
    float4 s = reinterpret_cast<const float4*>(bias)[o4];
    const float* p = g_part + (size_t)b * OUT_DIM + (size_t)o4 * 4;
#pragma unroll
    for (int z = 0; z < KSPLIT; ++z) {
        const float4 v = *reinterpret_cast<const float4*>(
            p + (size_t)z * B_DIM * OUT_DIM);
        s.x += v.x; s.y += v.y; s.z += v.z; s.w += v.w;
    }
    reinterpret_cast<float4*>(out)[(size_t)b * (OUT_DIM / 4) + o4] = s;
}

// ----------------------------------------------------------------------------
// kernel_launch: graph-capturable, allocation-free, deterministic.
// Inputs (metadata order): x f32[32,4096], codes i32[14336,4096],
//                          absmax f32[917504], bias f32[14336]
// Output: f32[32,14336]
// ----------------------------------------------------------------------------
extern "C" void kernel_launch(void* const* d_in, const int* in_sizes, int n_in,
                              void* d_out, int out_size)
{
    const float* x      = (const float*)d_in[0];
    const int*   codes  = (const int*)  d_in[1];
    const float* absmax = (const float*)d_in[2];
    const float* bias   = (const float*)d_in[3];
    float*       out    = (float*)d_out;

    dim3 grid(OUT_DIM / O_BLK, KSPLIT);           // (56, 16) = 896 blocks
    nf4_gemm_partial<<<grid, NTHREADS>>>(x, codes, absmax);

    const int n4 = B_DIM * OUT_DIM / 4;           // 114688
    nf4_reduce<<<n4 / 256, 256>>>(bias, out);     // 448 blocks, exact
}